// round 13
// baseline (speedup 1.0000x reference)
#include <cuda_runtime.h>
#include <cuda_fp16.h>
#include <math.h>

#define T_LEN 8192
#define EMB   512
#define HID   2048
#define NCH   256
#define ZDIM  2560        // EMB + HID
#define NBLK  128         // persistent CTAs (<=148 SMs, single wave)
#define UPB   16          // hidden units per block (128*16 = 2048)
#define SROWS 48          // gate rows per CTA kept resident in SMEM (of 64)
#define NLEAF 8           // barrier tree leaves (16 CTAs per leaf)

// Row ownership (balanced): warp w computes CTA-rows
//   {w*6 .. w*6+5}            from SMEM   (48 rows total)
//   {48+2w, 48+2w+1}          from L2      (16 rows total)
// CTA-row R in [0,64): gate = R>>4, unit = R&15.

// ---- static scratch (no runtime allocation allowed) ----
__device__ float    g_Gx[(size_t)T_LEN * 4 * HID];   // 256 MB: precomputed x-part + bias
__device__ float    g_H [(size_t)T_LEN * HID];       // 64 MB: all h_t for final Y GEMM
__device__ __half   g_Wh[(size_t)4 * HID * HID];     // 32 MB: fp16 recurrent weights
__device__ float    g_hbuf[2][HID];                  // double-buffered h broadcast
__device__ __align__(128) unsigned g_leaf[NLEAF];    // tree barrier counters (one line)

// ------------------------------------------------------------------
// init: reset leaf counters (must re-run per replay)
// ------------------------------------------------------------------
__global__ void init_kernel() {
    int tid = threadIdx.x;
    if (tid < NLEAF) g_leaf[tid] = 0u;
}

// ------------------------------------------------------------------
// prep: convert recurrent halves of W_f/i/c/o (cols EMB..ZDIM) to fp16.
// ------------------------------------------------------------------
__global__ void prep_kernel(const float* __restrict__ Wf, const float* __restrict__ Wi,
                            const float* __restrict__ Wc, const float* __restrict__ Wo)
{
    const int R = blockIdx.x;
    const int gate = R >> 11;
    const int j = R & (HID - 1);
    const float* W = (gate == 0) ? Wf : (gate == 1) ? Wi : (gate == 2) ? Wc : Wo;
    const float4* src = (const float4*)(W + (size_t)j * ZDIM + EMB);
    __half* dst = g_Wh + (size_t)R * HID;

    for (int c4 = threadIdx.x; c4 < HID / 4; c4 += blockDim.x) {
        float4 v = src[c4];
        __half2 lo = __floats2half2_rn(v.x, v.y);
        __half2 hi = __floats2half2_rn(v.z, v.w);
        *(uint2*)(dst + c4 * 4) = make_uint2(*(unsigned*)&lo, *(unsigned*)&hi);
    }
}

// ------------------------------------------------------------------
// Gx[t, gate*H + j] = b_gate[j] + sum_{k<512} emb[seq[t]][k] * W_gate[j][k]
// ------------------------------------------------------------------
__global__ void gx_kernel(const int* __restrict__ seq, const float* __restrict__ emb,
                          const float* __restrict__ Wf, const float* __restrict__ Wi,
                          const float* __restrict__ Wc, const float* __restrict__ Wo,
                          const float* __restrict__ bf, const float* __restrict__ bi,
                          const float* __restrict__ bc, const float* __restrict__ bo)
{
    __shared__ float xs[64][33];
    __shared__ float ws[64][33];
    __shared__ int   ss[64];
    __shared__ float bias_s[64];

    const int tid = threadIdx.x;
    const int t0 = blockIdx.x * 64;
    const int r0 = blockIdx.y * 64;
    const int gate = r0 >> 11;
    const int j0 = r0 & (HID - 1);

    const float* W  = (gate == 0) ? Wf : (gate == 1) ? Wi : (gate == 2) ? Wc : Wo;
    const float* bb = (gate == 0) ? bf : (gate == 1) ? bi : (gate == 2) ? bc : bo;

    if (tid < 64) { ss[tid] = seq[t0 + tid]; bias_s[tid] = bb[j0 + tid]; }

    const int tx = tid & 15, ty = tid >> 4;
    float acc[4][4];
    #pragma unroll
    for (int e = 0; e < 4; ++e)
        #pragma unroll
        for (int f = 0; f < 4; ++f) acc[e][f] = 0.f;

    for (int kc = 0; kc < EMB; kc += 32) {
        __syncthreads();
        #pragma unroll
        for (int i = 0; i < 8; ++i) {
            int l = tid + 256 * i;
            int row = l >> 5, col = l & 31;
            xs[row][col] = emb[(size_t)ss[row] * EMB + kc + col];
            ws[row][col] = W[(size_t)(j0 + row) * ZDIM + kc + col];
        }
        __syncthreads();
        #pragma unroll
        for (int k = 0; k < 32; ++k) {
            float a[4], b[4];
            #pragma unroll
            for (int e = 0; e < 4; ++e) a[e] = xs[ty * 4 + e][k];
            #pragma unroll
            for (int f = 0; f < 4; ++f) b[f] = ws[tx * 4 + f][k];
            #pragma unroll
            for (int e = 0; e < 4; ++e)
                #pragma unroll
                for (int f = 0; f < 4; ++f) acc[e][f] = fmaf(a[e], b[f], acc[e][f]);
        }
    }
    __syncthreads();
    #pragma unroll
    for (int e = 0; e < 4; ++e)
        #pragma unroll
        for (int f = 0; f < 4; ++f) {
            int t = t0 + ty * 4 + e;
            int r = r0 + tx * 4 + f;
            g_Gx[(size_t)t * (4 * HID) + r] = acc[e][f] + bias_s[tx * 4 + f];
        }
}

// ------------------------------------------------------------------
// Persistent sequential LSTM loop. 128 CTAs x 256 threads.
// R12 structure (balanced 6 smem + 2 streamed rows per warp).
// Barrier: fused warp-0 epilogue (gates -> syncwarp -> red.release
// arrive -> leaf-line spin -> fence.acq_rel). 3 syncthreads/step.
// ------------------------------------------------------------------
extern __shared__ unsigned char dynsmem[];

__device__ __forceinline__ float fast_sigmoid(float x) {
    return __fdividef(1.f, 1.f + __expf(-x));
}

__global__ void __launch_bounds__(256, 1) lstm_loop(float* __restrict__ out)
{
    __half* ws  = (__half*)dynsmem;                               // [SROWS][HID]
    float*  h_s = (float*)(dynsmem + (size_t)SROWS * HID * 2);    // [HID]
    __shared__ float g_s[64];
    __shared__ float gx_s[64];
    __shared__ float c_s[UPB];

    const int tid  = threadIdx.x;
    const int lane = tid & 31;
    const int w    = tid >> 5;
    const int blk  = blockIdx.x;
    const int sbase = w * 6;          // first SMEM CTA-row for this warp
    const int gbase = 48 + w * 2;     // first streamed CTA-row for this warp

    // ---- one-time: copy SMEM rows (CTA-rows 0..47) ----
    for (int idx = tid; idx < SROWS * (HID / 8); idx += 256) {
        int R  = idx / (HID / 8);
        int c8 = idx % (HID / 8);
        int gate = R >> 4, unit = R & 15;
        const uint4* src = (const uint4*)(g_Wh + ((size_t)(gate * HID + blk * UPB + unit)) * HID);
        ((uint4*)(ws + (size_t)R * HID))[c8] = src[c8];
    }

    // global row pointers for this warp's 2 streamed rows (CTA-rows 48..63)
    const __half* gp[2];
    #pragma unroll
    for (int r = 0; r < 2; ++r) {
        int R = gbase + r;
        int gate = R >> 4, unit = R & 15;
        gp[r] = g_Wh + ((size_t)(gate * HID + blk * UPB + unit)) * HID;
    }

    for (int i = tid; i < HID; i += 256) h_s[i] = 0.f;   // h_{-1} = 0
    if (tid < UPB) c_s[tid] = 0.f;
    __syncthreads();

    const float4* hs4 = (const float4*)h_s;

    for (int t = 0; t < T_LEN; ++t) {
        // prefetch Gx for this step (consumed at the gates stage)
        if (tid < 64)
            gx_s[tid] = __ldg(&g_Gx[(size_t)t * (4 * HID) + (tid >> 4) * HID
                                    + blk * UPB + (tid & 15)]);

        // ---- 8 dot products of length 2048 per warp: 6 smem + 2 global ----
        float4 acc[8];
        #pragma unroll
        for (int r = 0; r < 8; ++r) acc[r] = make_float4(0.f, 0.f, 0.f, 0.f);

        const __half* wrow = ws + (size_t)sbase * HID;
        #pragma unroll 4
        for (int kk = 0; kk < 16; ++kk) {
            const int off = kk * 128 + lane * 4;
            float4 h4 = hs4[kk * 32 + lane];
            // streamed rows first (get the LDGs in flight early)
            uint2 wg0 = __ldg((const uint2*)(gp[0] + off));
            uint2 wg1 = __ldg((const uint2*)(gp[1] + off));
            #pragma unroll
            for (int r = 0; r < 6; ++r) {
                uint2 wv = *(const uint2*)(wrow + (size_t)r * HID + off);
                float2 f01 = __half22float2(*(const __half2*)&wv.x);
                float2 f23 = __half22float2(*(const __half2*)&wv.y);
                acc[r].x = fmaf(f01.x, h4.x, acc[r].x);
                acc[r].y = fmaf(f01.y, h4.y, acc[r].y);
                acc[r].z = fmaf(f23.x, h4.z, acc[r].z);
                acc[r].w = fmaf(f23.y, h4.w, acc[r].w);
            }
            {
                float2 f01 = __half22float2(*(const __half2*)&wg0.x);
                float2 f23 = __half22float2(*(const __half2*)&wg0.y);
                acc[6].x = fmaf(f01.x, h4.x, acc[6].x);
                acc[6].y = fmaf(f01.y, h4.y, acc[6].y);
                acc[6].z = fmaf(f23.x, h4.z, acc[6].z);
                acc[6].w = fmaf(f23.y, h4.w, acc[6].w);
                f01 = __half22float2(*(const __half2*)&wg1.x);
                f23 = __half22float2(*(const __half2*)&wg1.y);
                acc[7].x = fmaf(f01.x, h4.x, acc[7].x);
                acc[7].y = fmaf(f01.y, h4.y, acc[7].y);
                acc[7].z = fmaf(f23.x, h4.z, acc[7].z);
                acc[7].w = fmaf(f23.y, h4.w, acc[7].w);
            }
        }

        #pragma unroll
        for (int r = 0; r < 8; ++r) {
            float s = (acc[r].x + acc[r].y) + (acc[r].z + acc[r].w);
            s += __shfl_xor_sync(0xFFFFFFFFu, s, 16);
            s += __shfl_xor_sync(0xFFFFFFFFu, s, 8);
            s += __shfl_xor_sync(0xFFFFFFFFu, s, 4);
            s += __shfl_xor_sync(0xFFFFFFFFu, s, 2);
            s += __shfl_xor_sync(0xFFFFFFFFu, s, 1);
            if (lane == 0) g_s[(r < 6) ? (sbase + r) : (gbase + r - 6)] = s;
        }
        __syncthreads();

        // ---- warp 0: gates -> publish -> release-arrive -> spin -> fence ----
        if (w == 0) {
            if (tid < UPB) {
                int j = blk * UPB + tid;
                float gf = g_s[tid]      + gx_s[tid];
                float gi = g_s[16 + tid] + gx_s[16 + tid];
                float gc = g_s[32 + tid] + gx_s[32 + tid];
                float go = g_s[48 + tid] + gx_s[48 + tid];
                float f_  = fast_sigmoid(gf);
                float i_  = fast_sigmoid(gi);
                float ct  = __tanhf(gc);
                float o_  = fast_sigmoid(go);
                float c   = f_ * c_s[tid] + i_ * ct;
                c_s[tid]  = c;
                float h   = o_ * __tanhf(c);
                __stcg(&g_hbuf[t & 1][j], h);
                __stcg(&g_H[(size_t)t * HID + j], h);
                if (t == T_LEN - 1) {
                    out[(size_t)T_LEN * NCH + j]       = h;   // final h
                    out[(size_t)T_LEN * NCH + HID + j] = c;   // final c
                }
            }
            __syncwarp();
            if (tid == 0) {
                // release-arrive orders the h stores; no separate MEMBAR
                asm volatile("red.release.gpu.global.add.u32 [%0], %1;"
                             :: "l"(&g_leaf[blk >> 4]), "r"(1u) : "memory");
                const unsigned target = (unsigned)(t + 1) * 16u;
                unsigned long long a0 = (unsigned long long)&g_leaf[0];
                unsigned long long a1 = (unsigned long long)&g_leaf[4];
                for (;;) {
                    unsigned x0, x1, x2, x3, y0, y1, y2, y3;
                    asm volatile("ld.volatile.global.v4.u32 {%0,%1,%2,%3}, [%4];"
                                 : "=r"(x0), "=r"(x1), "=r"(x2), "=r"(x3)
                                 : "l"(a0) : "memory");
                    asm volatile("ld.volatile.global.v4.u32 {%0,%1,%2,%3}, [%4];"
                                 : "=r"(y0), "=r"(y1), "=r"(y2), "=r"(y3)
                                 : "l"(a1) : "memory");
                    if (x0 >= target && x1 >= target && x2 >= target && x3 >= target &&
                        y0 >= target && y1 >= target && y2 >= target && y3 >= target)
                        break;
                }
                asm volatile("fence.acq_rel.gpu;" ::: "memory");
            }
        }
        __syncthreads();

        // ---- parallel gather of full h(t): 2 float4 per thread ----
        {
            const float4* src = (const float4*)g_hbuf[t & 1];
            float4* dst = (float4*)h_s;
            dst[tid]       = __ldcg(&src[tid]);
            dst[tid + 256] = __ldcg(&src[tid + 256]);
        }
        __syncthreads();
    }
}

// ------------------------------------------------------------------
// Y[t][n] = b_y[n] + sum_k H[t][k] * W_y[n][k]
// ------------------------------------------------------------------
__global__ void y_kernel(const float* __restrict__ Wy, const float* __restrict__ by,
                         float* __restrict__ out)
{
    __shared__ float as[64][33];
    __shared__ float ws[64][33];
    __shared__ float bias_s[64];

    const int tid = threadIdx.x;
    const int t0 = blockIdx.x * 64;
    const int n0 = blockIdx.y * 64;
    if (tid < 64) bias_s[tid] = by[n0 + tid];

    const int tx = tid & 15, ty = tid >> 4;
    float acc[4][4];
    #pragma unroll
    for (int e = 0; e < 4; ++e)
        #pragma unroll
        for (int f = 0; f < 4; ++f) acc[e][f] = 0.f;

    for (int kc = 0; kc < HID; kc += 32) {
        __syncthreads();
        #pragma unroll
        for (int i = 0; i < 8; ++i) {
            int l = tid + 256 * i;
            int row = l >> 5, col = l & 31;
            as[row][col] = g_H[(size_t)(t0 + row) * HID + kc + col];
            ws[row][col] = Wy[(size_t)(n0 + row) * HID + kc + col];
        }
        __syncthreads();
        #pragma unroll
        for (int k = 0; k < 32; ++k) {
            float a[4], b[4];
            #pragma unroll
            for (int e = 0; e < 4; ++e) a[e] = as[ty * 4 + e][k];
            #pragma unroll
            for (int f = 0; f < 4; ++f) b[f] = ws[tx * 4 + f][k];
            #pragma unroll
            for (int e = 0; e < 4; ++e)
                #pragma unroll
                for (int f = 0; f < 4; ++f) acc[e][f] = fmaf(a[e], b[f], acc[e][f]);
        }
    }
    __syncthreads();
    #pragma unroll
    for (int e = 0; e < 4; ++e)
        #pragma unroll
        for (int f = 0; f < 4; ++f)
            out[(size_t)(t0 + ty * 4 + e) * NCH + n0 + tx * 4 + f]
                = acc[e][f] + bias_s[tx * 4 + f];
}

// ------------------------------------------------------------------
extern "C" void kernel_launch(void* const* d_in, const int* in_sizes, int n_in,
                              void* d_out, int out_size)
{
    const int*   seq = (const int*)  d_in[0];
    const float* emb = (const float*)d_in[1];
    const float* Wf  = (const float*)d_in[2];
    const float* bf  = (const float*)d_in[3];
    const float* Wi  = (const float*)d_in[4];
    const float* bi  = (const float*)d_in[5];
    const float* Wo  = (const float*)d_in[6];
    const float* bo  = (const float*)d_in[7];
    const float* Wc  = (const float*)d_in[8];
    const float* bc  = (const float*)d_in[9];
    const float* Wy  = (const float*)d_in[10];
    const float* by  = (const float*)d_in[11];
    float* out = (float*)d_out;

    const int dyn_smem = SROWS * HID * 2 + HID * 4;   // 204800 B
    cudaFuncSetAttribute(lstm_loop, cudaFuncAttributeMaxDynamicSharedMemorySize, dyn_smem);

    init_kernel<<<1, 256>>>();

    prep_kernel<<<4 * HID, 256>>>(Wf, Wi, Wc, Wo);

    dim3 ggx(T_LEN / 64, (4 * HID) / 64);          // 128 x 128
    gx_kernel<<<ggx, 256>>>(seq, emb, Wf, Wi, Wc, Wo, bf, bi, bc, bo);

    lstm_loop<<<NBLK, 256, dyn_smem>>>(out);

    dim3 gy(T_LEN / 64, NCH / 64);                 // 128 x 4
    y_kernel<<<gy, 256>>>(Wy, by, out);
}

// round 14
// speedup vs baseline: 1.0471x; 1.0471x over previous
#include <cuda_runtime.h>
#include <cuda_fp16.h>
#include <math.h>

#define T_LEN 8192
#define EMB   512
#define HID   2048
#define NCH   256
#define ZDIM  2560        // EMB + HID
#define NBLK  128         // persistent CTAs (<=148 SMs, single wave)
#define UPB   16          // hidden units per block (128*16 = 2048)
#define SROWS 48          // gate rows per CTA kept resident in SMEM (of 64)
#define NLEAF 8           // barrier tree leaves (16 CTAs per leaf)

// Row ownership (balanced): warp w computes CTA-rows
//   {w*6 .. w*6+5}            from SMEM   (48 rows total)
//   {48+2w, 48+2w+1}          from L2      (16 rows total)
// CTA-row R in [0,64): gate = R>>4, unit = R&15.

// ---- static scratch (no runtime allocation allowed) ----
__device__ float    g_Gx[(size_t)T_LEN * 4 * HID];   // 256 MB: precomputed x-part + bias
__device__ float    g_H [(size_t)T_LEN * HID];       // 64 MB: all h_t for final Y GEMM
__device__ __half   g_Wh[(size_t)4 * HID * HID];     // 32 MB: fp16 recurrent weights
__device__ float    g_hbuf[2][HID];                  // double-buffered h broadcast
__device__ __align__(128) unsigned g_leaf[NLEAF];    // tree barrier counters (one line)

// ------------------------------------------------------------------
// init: reset leaf counters (must re-run per replay)
// ------------------------------------------------------------------
__global__ void init_kernel() {
    int tid = threadIdx.x;
    if (tid < NLEAF) g_leaf[tid] = 0u;
}

// ------------------------------------------------------------------
// prep: convert recurrent halves of W_f/i/c/o (cols EMB..ZDIM) to fp16.
// ------------------------------------------------------------------
__global__ void prep_kernel(const float* __restrict__ Wf, const float* __restrict__ Wi,
                            const float* __restrict__ Wc, const float* __restrict__ Wo)
{
    const int R = blockIdx.x;
    const int gate = R >> 11;
    const int j = R & (HID - 1);
    const float* W = (gate == 0) ? Wf : (gate == 1) ? Wi : (gate == 2) ? Wc : Wo;
    const float4* src = (const float4*)(W + (size_t)j * ZDIM + EMB);
    __half* dst = g_Wh + (size_t)R * HID;

    for (int c4 = threadIdx.x; c4 < HID / 4; c4 += blockDim.x) {
        float4 v = src[c4];
        __half2 lo = __floats2half2_rn(v.x, v.y);
        __half2 hi = __floats2half2_rn(v.z, v.w);
        *(uint2*)(dst + c4 * 4) = make_uint2(*(unsigned*)&lo, *(unsigned*)&hi);
    }
}

// ------------------------------------------------------------------
// Gx[t, gate*H + j] = b_gate[j] + sum_{k<512} emb[seq[t]][k] * W_gate[j][k]
// ------------------------------------------------------------------
__global__ void gx_kernel(const int* __restrict__ seq, const float* __restrict__ emb,
                          const float* __restrict__ Wf, const float* __restrict__ Wi,
                          const float* __restrict__ Wc, const float* __restrict__ Wo,
                          const float* __restrict__ bf, const float* __restrict__ bi,
                          const float* __restrict__ bc, const float* __restrict__ bo)
{
    __shared__ float xs[64][33];
    __shared__ float ws[64][33];
    __shared__ int   ss[64];
    __shared__ float bias_s[64];

    const int tid = threadIdx.x;
    const int t0 = blockIdx.x * 64;
    const int r0 = blockIdx.y * 64;
    const int gate = r0 >> 11;
    const int j0 = r0 & (HID - 1);

    const float* W  = (gate == 0) ? Wf : (gate == 1) ? Wi : (gate == 2) ? Wc : Wo;
    const float* bb = (gate == 0) ? bf : (gate == 1) ? bi : (gate == 2) ? bc : bo;

    if (tid < 64) { ss[tid] = seq[t0 + tid]; bias_s[tid] = bb[j0 + tid]; }

    const int tx = tid & 15, ty = tid >> 4;
    float acc[4][4];
    #pragma unroll
    for (int e = 0; e < 4; ++e)
        #pragma unroll
        for (int f = 0; f < 4; ++f) acc[e][f] = 0.f;

    for (int kc = 0; kc < EMB; kc += 32) {
        __syncthreads();
        #pragma unroll
        for (int i = 0; i < 8; ++i) {
            int l = tid + 256 * i;
            int row = l >> 5, col = l & 31;
            xs[row][col] = emb[(size_t)ss[row] * EMB + kc + col];
            ws[row][col] = W[(size_t)(j0 + row) * ZDIM + kc + col];
        }
        __syncthreads();
        #pragma unroll
        for (int k = 0; k < 32; ++k) {
            float a[4], b[4];
            #pragma unroll
            for (int e = 0; e < 4; ++e) a[e] = xs[ty * 4 + e][k];
            #pragma unroll
            for (int f = 0; f < 4; ++f) b[f] = ws[tx * 4 + f][k];
            #pragma unroll
            for (int e = 0; e < 4; ++e)
                #pragma unroll
                for (int f = 0; f < 4; ++f) acc[e][f] = fmaf(a[e], b[f], acc[e][f]);
        }
    }
    __syncthreads();
    #pragma unroll
    for (int e = 0; e < 4; ++e)
        #pragma unroll
        for (int f = 0; f < 4; ++f) {
            int t = t0 + ty * 4 + e;
            int r = r0 + tx * 4 + f;
            g_Gx[(size_t)t * (4 * HID) + r] = acc[e][f] + bias_s[tx * 4 + f];
        }
}

// ------------------------------------------------------------------
// Persistent sequential LSTM loop. 128 CTAs x 256 threads.
// R12 structure (balanced 6 smem + 2 streamed rows per warp).
// NEW: Gx prefetched one FULL step ahead (DRAM tail fully hidden),
//      tanh-form sigmoid (shorter MUFU chain in gates).
// ------------------------------------------------------------------
extern __shared__ unsigned char dynsmem[];

__device__ __forceinline__ float fast_sigmoid(float x) {
    // sigmoid(x) = 0.5 + 0.5*tanh(0.5*x): FMUL + MUFU.TANH + FFMA
    return fmaf(__tanhf(0.5f * x), 0.5f, 0.5f);
}

__global__ void __launch_bounds__(256, 1) lstm_loop(float* __restrict__ out)
{
    __half* ws  = (__half*)dynsmem;                               // [SROWS][HID]
    float*  h_s = (float*)(dynsmem + (size_t)SROWS * HID * 2);    // [HID]
    __shared__ float g_s[64];
    __shared__ float gx_s[64];
    __shared__ float c_s[UPB];

    const int tid  = threadIdx.x;
    const int lane = tid & 31;
    const int w    = tid >> 5;
    const int blk  = blockIdx.x;
    const int sbase = w * 6;          // first SMEM CTA-row for this warp
    const int gbase = 48 + w * 2;     // first streamed CTA-row for this warp

    // ---- one-time: copy SMEM rows (CTA-rows 0..47) ----
    for (int idx = tid; idx < SROWS * (HID / 8); idx += 256) {
        int R  = idx / (HID / 8);
        int c8 = idx % (HID / 8);
        int gate = R >> 4, unit = R & 15;
        const uint4* src = (const uint4*)(g_Wh + ((size_t)(gate * HID + blk * UPB + unit)) * HID);
        ((uint4*)(ws + (size_t)R * HID))[c8] = src[c8];
    }

    // global row pointers for this warp's 2 streamed rows (CTA-rows 48..63)
    const __half* gp[2];
    #pragma unroll
    for (int r = 0; r < 2; ++r) {
        int R = gbase + r;
        int gate = R >> 4, unit = R & 15;
        gp[r] = g_Wh + ((size_t)(gate * HID + blk * UPB + unit)) * HID;
    }

    for (int i = tid; i < HID; i += 256) h_s[i] = 0.f;   // h_{-1} = 0
    if (tid < UPB) c_s[tid] = 0.f;

    // ---- Gx pipeline: gxp holds Gx for the CURRENT step at loop top ----
    const size_t gx_off = (size_t)(tid >> 4) * HID + blk * UPB + (tid & 15);
    float gxp = 0.f;
    if (tid < 64) gxp = __ldg(&g_Gx[gx_off]);            // step 0
    __syncthreads();

    const float4* hs4 = (const float4*)h_s;

    for (int t = 0; t < T_LEN; ++t) {
        // publish current-step Gx to smem; issue NEXT step's load (full step of slack)
        if (tid < 64) {
            gx_s[tid] = gxp;
            int tn = (t + 1 < T_LEN) ? (t + 1) : t;
            gxp = __ldg(&g_Gx[(size_t)tn * (4 * HID) + gx_off]);
        }

        // ---- 8 dot products of length 2048 per warp: 6 smem + 2 global ----
        float4 acc[8];
        #pragma unroll
        for (int r = 0; r < 8; ++r) acc[r] = make_float4(0.f, 0.f, 0.f, 0.f);

        const __half* wrow = ws + (size_t)sbase * HID;
        #pragma unroll 4
        for (int kk = 0; kk < 16; ++kk) {
            const int off = kk * 128 + lane * 4;
            float4 h4 = hs4[kk * 32 + lane];
            // streamed rows first (get the LDGs in flight early)
            uint2 wg0 = __ldg((const uint2*)(gp[0] + off));
            uint2 wg1 = __ldg((const uint2*)(gp[1] + off));
            #pragma unroll
            for (int r = 0; r < 6; ++r) {
                uint2 wv = *(const uint2*)(wrow + (size_t)r * HID + off);
                float2 f01 = __half22float2(*(const __half2*)&wv.x);
                float2 f23 = __half22float2(*(const __half2*)&wv.y);
                acc[r].x = fmaf(f01.x, h4.x, acc[r].x);
                acc[r].y = fmaf(f01.y, h4.y, acc[r].y);
                acc[r].z = fmaf(f23.x, h4.z, acc[r].z);
                acc[r].w = fmaf(f23.y, h4.w, acc[r].w);
            }
            {
                float2 f01 = __half22float2(*(const __half2*)&wg0.x);
                float2 f23 = __half22float2(*(const __half2*)&wg0.y);
                acc[6].x = fmaf(f01.x, h4.x, acc[6].x);
                acc[6].y = fmaf(f01.y, h4.y, acc[6].y);
                acc[6].z = fmaf(f23.x, h4.z, acc[6].z);
                acc[6].w = fmaf(f23.y, h4.w, acc[6].w);
                f01 = __half22float2(*(const __half2*)&wg1.x);
                f23 = __half22float2(*(const __half2*)&wg1.y);
                acc[7].x = fmaf(f01.x, h4.x, acc[7].x);
                acc[7].y = fmaf(f01.y, h4.y, acc[7].y);
                acc[7].z = fmaf(f23.x, h4.z, acc[7].z);
                acc[7].w = fmaf(f23.y, h4.w, acc[7].w);
            }
        }

        #pragma unroll
        for (int r = 0; r < 8; ++r) {
            float s = (acc[r].x + acc[r].y) + (acc[r].z + acc[r].w);
            s += __shfl_xor_sync(0xFFFFFFFFu, s, 16);
            s += __shfl_xor_sync(0xFFFFFFFFu, s, 8);
            s += __shfl_xor_sync(0xFFFFFFFFu, s, 4);
            s += __shfl_xor_sync(0xFFFFFFFFu, s, 2);
            s += __shfl_xor_sync(0xFFFFFFFFu, s, 1);
            if (lane == 0) g_s[(r < 6) ? (sbase + r) : (gbase + r - 6)] = s;
        }
        __syncthreads();

        // ---- pointwise gates (16 threads, one per owned unit) ----
        if (tid < UPB) {
            int j = blk * UPB + tid;
            float gf = g_s[tid]      + gx_s[tid];
            float gi = g_s[16 + tid] + gx_s[16 + tid];
            float gc = g_s[32 + tid] + gx_s[32 + tid];
            float go = g_s[48 + tid] + gx_s[48 + tid];
            float f_  = fast_sigmoid(gf);
            float i_  = fast_sigmoid(gi);
            float ct  = __tanhf(gc);
            float o_  = fast_sigmoid(go);
            float c   = f_ * c_s[tid] + i_ * ct;
            c_s[tid]  = c;
            float h   = o_ * __tanhf(c);
            __stcg(&g_hbuf[t & 1][j], h);
            __stcg(&g_H[(size_t)t * HID + j], h);
            if (t == T_LEN - 1) {
                out[(size_t)T_LEN * NCH + j]       = h;   // final h
                out[(size_t)T_LEN * NCH + HID + j] = c;   // final c
            }
        }
        __syncthreads();

        // ---- tree barrier: arrive on leaf, spin on the single counter line ----
        if (tid == 0) {
            __threadfence();
            atomicAdd(&g_leaf[blk >> 4], 1u);
            const unsigned target = (unsigned)(t + 1) * 16u;
            unsigned long long a0 = (unsigned long long)&g_leaf[0];
            unsigned long long a1 = (unsigned long long)&g_leaf[4];
            for (;;) {
                unsigned x0, x1, x2, x3, y0, y1, y2, y3;
                asm volatile("ld.volatile.global.v4.u32 {%0,%1,%2,%3}, [%4];"
                             : "=r"(x0), "=r"(x1), "=r"(x2), "=r"(x3)
                             : "l"(a0) : "memory");
                asm volatile("ld.volatile.global.v4.u32 {%0,%1,%2,%3}, [%4];"
                             : "=r"(y0), "=r"(y1), "=r"(y2), "=r"(y3)
                             : "l"(a1) : "memory");
                if (x0 >= target && x1 >= target && x2 >= target && x3 >= target &&
                    y0 >= target && y1 >= target && y2 >= target && y3 >= target)
                    break;
            }
            __threadfence();
        }
        __syncthreads();

        // ---- parallel gather of full h(t): 2 float4 per thread ----
        {
            const float4* src = (const float4*)g_hbuf[t & 1];
            float4* dst = (float4*)h_s;
            dst[tid]       = __ldcg(&src[tid]);
            dst[tid + 256] = __ldcg(&src[tid + 256]);
        }
        __syncthreads();
    }
}

// ------------------------------------------------------------------
// Y[t][n] = b_y[n] + sum_k H[t][k] * W_y[n][k]
// ------------------------------------------------------------------
__global__ void y_kernel(const float* __restrict__ Wy, const float* __restrict__ by,
                         float* __restrict__ out)
{
    __shared__ float as[64][33];
    __shared__ float ws[64][33];
    __shared__ float bias_s[64];

    const int tid = threadIdx.x;
    const int t0 = blockIdx.x * 64;
    const int n0 = blockIdx.y * 64;
    if (tid < 64) bias_s[tid] = by[n0 + tid];

    const int tx = tid & 15, ty = tid >> 4;
    float acc[4][4];
    #pragma unroll
    for (int e = 0; e < 4; ++e)
        #pragma unroll
        for (int f = 0; f < 4; ++f) acc[e][f] = 0.f;

    for (int kc = 0; kc < HID; kc += 32) {
        __syncthreads();
        #pragma unroll
        for (int i = 0; i < 8; ++i) {
            int l = tid + 256 * i;
            int row = l >> 5, col = l & 31;
            as[row][col] = g_H[(size_t)(t0 + row) * HID + kc + col];
            ws[row][col] = Wy[(size_t)(n0 + row) * HID + kc + col];
        }
        __syncthreads();
        #pragma unroll
        for (int k = 0; k < 32; ++k) {
            float a[4], b[4];
            #pragma unroll
            for (int e = 0; e < 4; ++e) a[e] = as[ty * 4 + e][k];
            #pragma unroll
            for (int f = 0; f < 4; ++f) b[f] = ws[tx * 4 + f][k];
            #pragma unroll
            for (int e = 0; e < 4; ++e)
                #pragma unroll
                for (int f = 0; f < 4; ++f) acc[e][f] = fmaf(a[e], b[f], acc[e][f]);
        }
    }
    __syncthreads();
    #pragma unroll
    for (int e = 0; e < 4; ++e)
        #pragma unroll
        for (int f = 0; f < 4; ++f)
            out[(size_t)(t0 + ty * 4 + e) * NCH + n0 + tx * 4 + f]
                = acc[e][f] + bias_s[tx * 4 + f];
}

// ------------------------------------------------------------------
extern "C" void kernel_launch(void* const* d_in, const int* in_sizes, int n_in,
                              void* d_out, int out_size)
{
    const int*   seq = (const int*)  d_in[0];
    const float* emb = (const float*)d_in[1];
    const float* Wf  = (const float*)d_in[2];
    const float* bf  = (const float*)d_in[3];
    const float* Wi  = (const float*)d_in[4];
    const float* bi  = (const float*)d_in[5];
    const float* Wo  = (const float*)d_in[6];
    const float* bo  = (const float*)d_in[7];
    const float* Wc  = (const float*)d_in[8];
    const float* bc  = (const float*)d_in[9];
    const float* Wy  = (const float*)d_in[10];
    const float* by  = (const float*)d_in[11];
    float* out = (float*)d_out;

    const int dyn_smem = SROWS * HID * 2 + HID * 4;   // 204800 B
    cudaFuncSetAttribute(lstm_loop, cudaFuncAttributeMaxDynamicSharedMemorySize, dyn_smem);

    init_kernel<<<1, 256>>>();

    prep_kernel<<<4 * HID, 256>>>(Wf, Wi, Wc, Wo);

    dim3 ggx(T_LEN / 64, (4 * HID) / 64);          // 128 x 128
    gx_kernel<<<ggx, 256>>>(seq, emb, Wf, Wi, Wc, Wo, bf, bi, bc, bo);

    lstm_loop<<<NBLK, 256, dyn_smem>>>(out);

    dim3 gy(T_LEN / 64, NCH / 64);                 // 128 x 4
    y_kernel<<<gy, 256>>>(Wy, by, out);
}

// round 17
// speedup vs baseline: 1.1145x; 1.0644x over previous
#include <cuda_runtime.h>
#include <cuda_fp16.h>
#include <math.h>

#define T_LEN 8192
#define EMB   512
#define HID   2048
#define NCH   256
#define ZDIM  2560        // EMB + HID
#define NBLK  128         // persistent CTAs (<=148 SMs, single wave)
#define NTHR  512         // threads per CTA (16 warps, 4 per SMSP)
#define UPB   16          // hidden units per block (128*16 = 2048)
#define SROWS 48          // gate rows per CTA kept resident in SMEM (of 64)
#define NLEAF 8           // barrier tree leaves (16 CTAs per leaf)

// Row ownership (balanced, 16 warps): warp w computes CTA-rows
//   {3w, 3w+1, 3w+2}   from SMEM  (48 rows total)
//   {48 + w}           from L2    (16 rows total)
// CTA-row R in [0,64): gate = R>>4, unit = R&15.

// ---- static scratch (no runtime allocation allowed) ----
__device__ float    g_Gx[(size_t)T_LEN * 4 * HID];   // 256 MB: precomputed x-part + bias
__device__ float    g_H [(size_t)T_LEN * HID];       // 64 MB: all h_t for final Y GEMM
__device__ __half   g_Wh[(size_t)4 * HID * HID];     // 32 MB: fp16 recurrent weights
__device__ float    g_hbuf[2][HID];                  // double-buffered h broadcast
__device__ __align__(128) unsigned g_leaf[NLEAF];    // tree barrier counters (one line)

// ------------------------------------------------------------------
// init: reset leaf counters (must re-run per replay)
// ------------------------------------------------------------------
__global__ void init_kernel() {
    int tid = threadIdx.x;
    if (tid < NLEAF) g_leaf[tid] = 0u;
}

// ------------------------------------------------------------------
// prep: convert recurrent halves of W_f/i/c/o (cols EMB..ZDIM) to fp16.
// ------------------------------------------------------------------
__global__ void prep_kernel(const float* __restrict__ Wf, const float* __restrict__ Wi,
                            const float* __restrict__ Wc, const float* __restrict__ Wo)
{
    const int R = blockIdx.x;
    const int gate = R >> 11;
    const int j = R & (HID - 1);
    const float* W = (gate == 0) ? Wf : (gate == 1) ? Wi : (gate == 2) ? Wc : Wo;
    const float4* src = (const float4*)(W + (size_t)j * ZDIM + EMB);
    __half* dst = g_Wh + (size_t)R * HID;

    for (int c4 = threadIdx.x; c4 < HID / 4; c4 += blockDim.x) {
        float4 v = src[c4];
        __half2 lo = __floats2half2_rn(v.x, v.y);
        __half2 hi = __floats2half2_rn(v.z, v.w);
        *(uint2*)(dst + c4 * 4) = make_uint2(*(unsigned*)&lo, *(unsigned*)&hi);
    }
}

// ------------------------------------------------------------------
// Gx[t, gate*H + j] = b_gate[j] + sum_{k<512} emb[seq[t]][k] * W_gate[j][k]
// ------------------------------------------------------------------
__global__ void gx_kernel(const int* __restrict__ seq, const float* __restrict__ emb,
                          const float* __restrict__ Wf, const float* __restrict__ Wi,
                          const float* __restrict__ Wc, const float* __restrict__ Wo,
                          const float* __restrict__ bf, const float* __restrict__ bi,
                          const float* __restrict__ bc, const float* __restrict__ bo)
{
    __shared__ float xs[64][33];
    __shared__ float ws[64][33];
    __shared__ int   ss[64];
    __shared__ float bias_s[64];

    const int tid = threadIdx.x;
    const int t0 = blockIdx.x * 64;
    const int r0 = blockIdx.y * 64;
    const int gate = r0 >> 11;
    const int j0 = r0 & (HID - 1);

    const float* W  = (gate == 0) ? Wf : (gate == 1) ? Wi : (gate == 2) ? Wc : Wo;
    const float* bb = (gate == 0) ? bf : (gate == 1) ? bi : (gate == 2) ? bc : bo;

    if (tid < 64) { ss[tid] = seq[t0 + tid]; bias_s[tid] = bb[j0 + tid]; }

    const int tx = tid & 15, ty = tid >> 4;
    float acc[4][4];
    #pragma unroll
    for (int e = 0; e < 4; ++e)
        #pragma unroll
        for (int f = 0; f < 4; ++f) acc[e][f] = 0.f;

    for (int kc = 0; kc < EMB; kc += 32) {
        __syncthreads();
        #pragma unroll
        for (int i = 0; i < 8; ++i) {
            int l = tid + 256 * i;
            int row = l >> 5, col = l & 31;
            xs[row][col] = emb[(size_t)ss[row] * EMB + kc + col];
            ws[row][col] = W[(size_t)(j0 + row) * ZDIM + kc + col];
        }
        __syncthreads();
        #pragma unroll
        for (int k = 0; k < 32; ++k) {
            float a[4], b[4];
            #pragma unroll
            for (int e = 0; e < 4; ++e) a[e] = xs[ty * 4 + e][k];
            #pragma unroll
            for (int f = 0; f < 4; ++f) b[f] = ws[tx * 4 + f][k];
            #pragma unroll
            for (int e = 0; e < 4; ++e)
                #pragma unroll
                for (int f = 0; f < 4; ++f) acc[e][f] = fmaf(a[e], b[f], acc[e][f]);
        }
    }
    __syncthreads();
    #pragma unroll
    for (int e = 0; e < 4; ++e)
        #pragma unroll
        for (int f = 0; f < 4; ++f) {
            int t = t0 + ty * 4 + e;
            int r = r0 + tx * 4 + f;
            g_Gx[(size_t)t * (4 * HID) + r] = acc[e][f] + bias_s[tx * 4 + f];
        }
}

// ------------------------------------------------------------------
// Persistent sequential LSTM loop. 128 CTAs x 512 threads (16 warps).
// Balanced rows: 3 SMEM + 1 streamed per warp. Gx prefetched one full
// step ahead; tree barrier; parallel gather (1 float4 per thread).
// ------------------------------------------------------------------
extern __shared__ unsigned char dynsmem[];

__device__ __forceinline__ float fast_sigmoid(float x) {
    // sigmoid(x) = 0.5 + 0.5*tanh(0.5*x): FMUL + MUFU.TANH + FFMA
    return fmaf(__tanhf(0.5f * x), 0.5f, 0.5f);
}

__global__ void __launch_bounds__(NTHR, 1) lstm_loop(float* __restrict__ out)
{
    __half* ws  = (__half*)dynsmem;                               // [SROWS][HID]
    float*  h_s = (float*)(dynsmem + (size_t)SROWS * HID * 2);    // [HID]
    __shared__ float g_s[64];
    __shared__ float gx_s[64];
    __shared__ float c_s[UPB];

    const int tid  = threadIdx.x;
    const int lane = tid & 31;
    const int w    = tid >> 5;        // warp 0..15
    const int blk  = blockIdx.x;
    const int sbase = w * 3;          // first SMEM CTA-row for this warp
    const int grow  = 48 + w;         // streamed CTA-row for this warp

    // ---- one-time: copy SMEM rows (CTA-rows 0..47) ----
    for (int idx = tid; idx < SROWS * (HID / 8); idx += NTHR) {
        int R  = idx / (HID / 8);
        int c8 = idx % (HID / 8);
        int gate = R >> 4, unit = R & 15;
        const uint4* src = (const uint4*)(g_Wh + ((size_t)(gate * HID + blk * UPB + unit)) * HID);
        ((uint4*)(ws + (size_t)R * HID))[c8] = src[c8];
    }

    // global row pointer for this warp's streamed row (CTA-rows 48..63)
    const __half* gp;
    {
        int gate = grow >> 4, unit = grow & 15;
        gp = g_Wh + ((size_t)(gate * HID + blk * UPB + unit)) * HID;
    }

    for (int i = tid; i < HID; i += NTHR) h_s[i] = 0.f;   // h_{-1} = 0
    if (tid < UPB) c_s[tid] = 0.f;

    // ---- Gx pipeline: gxp holds Gx for the CURRENT step at loop top ----
    const size_t gx_off = (size_t)(tid >> 4) * HID + blk * UPB + (tid & 15);
    float gxp = 0.f;
    if (tid < 64) gxp = __ldg(&g_Gx[gx_off]);            // step 0
    __syncthreads();

    const float4* hs4 = (const float4*)h_s;

    for (int t = 0; t < T_LEN; ++t) {
        // publish current-step Gx to smem; issue NEXT step's load (full step of slack)
        if (tid < 64) {
            gx_s[tid] = gxp;
            int tn = (t + 1 < T_LEN) ? (t + 1) : t;
            gxp = __ldg(&g_Gx[(size_t)tn * (4 * HID) + gx_off]);
        }

        // ---- 4 dot products of length 2048 per warp: 3 smem + 1 global ----
        float4 acc[4];
        #pragma unroll
        for (int r = 0; r < 4; ++r) acc[r] = make_float4(0.f, 0.f, 0.f, 0.f);

        const __half* wrow = ws + (size_t)sbase * HID;
        #pragma unroll 4
        for (int kk = 0; kk < 16; ++kk) {
            const int off = kk * 128 + lane * 4;
            float4 h4 = hs4[kk * 32 + lane];
            // streamed row first (get the LDG in flight early)
            uint2 wg0 = __ldg((const uint2*)(gp + off));
            #pragma unroll
            for (int r = 0; r < 3; ++r) {
                uint2 wv = *(const uint2*)(wrow + (size_t)r * HID + off);
                float2 f01 = __half22float2(*(const __half2*)&wv.x);
                float2 f23 = __half22float2(*(const __half2*)&wv.y);
                acc[r].x = fmaf(f01.x, h4.x, acc[r].x);
                acc[r].y = fmaf(f01.y, h4.y, acc[r].y);
                acc[r].z = fmaf(f23.x, h4.z, acc[r].z);
                acc[r].w = fmaf(f23.y, h4.w, acc[r].w);
            }
            {
                float2 f01 = __half22float2(*(const __half2*)&wg0.x);
                float2 f23 = __half22float2(*(const __half2*)&wg0.y);
                acc[3].x = fmaf(f01.x, h4.x, acc[3].x);
                acc[3].y = fmaf(f01.y, h4.y, acc[3].y);
                acc[3].z = fmaf(f23.x, h4.z, acc[3].z);
                acc[3].w = fmaf(f23.y, h4.w, acc[3].w);
            }
        }

        #pragma unroll
        for (int r = 0; r < 4; ++r) {
            float s = (acc[r].x + acc[r].y) + (acc[r].z + acc[r].w);
            s += __shfl_xor_sync(0xFFFFFFFFu, s, 16);
            s += __shfl_xor_sync(0xFFFFFFFFu, s, 8);
            s += __shfl_xor_sync(0xFFFFFFFFu, s, 4);
            s += __shfl_xor_sync(0xFFFFFFFFu, s, 2);
            s += __shfl_xor_sync(0xFFFFFFFFu, s, 1);
            if (lane == 0) g_s[(r < 3) ? (sbase + r) : grow] = s;
        }
        __syncthreads();

        // ---- pointwise gates (16 threads, one per owned unit) ----
        if (tid < UPB) {
            int j = blk * UPB + tid;
            float gf = g_s[tid]      + gx_s[tid];
            float gi = g_s[16 + tid] + gx_s[16 + tid];
            float gc = g_s[32 + tid] + gx_s[32 + tid];
            float go = g_s[48 + tid] + gx_s[48 + tid];
            float f_  = fast_sigmoid(gf);
            float i_  = fast_sigmoid(gi);
            float ct  = __tanhf(gc);
            float o_  = fast_sigmoid(go);
            float c   = f_ * c_s[tid] + i_ * ct;
            c_s[tid]  = c;
            float h   = o_ * __tanhf(c);
            __stcg(&g_hbuf[t & 1][j], h);
            __stcg(&g_H[(size_t)t * HID + j], h);
            if (t == T_LEN - 1) {
                out[(size_t)T_LEN * NCH + j]       = h;   // final h
                out[(size_t)T_LEN * NCH + HID + j] = c;   // final c
            }
        }
        __syncthreads();

        // ---- tree barrier: arrive on leaf, spin on the single counter line ----
        if (tid == 0) {
            __threadfence();
            atomicAdd(&g_leaf[blk >> 4], 1u);
            const unsigned target = (unsigned)(t + 1) * 16u;
            unsigned long long a0 = (unsigned long long)&g_leaf[0];
            unsigned long long a1 = (unsigned long long)&g_leaf[4];
            for (;;) {
                unsigned x0, x1, x2, x3, y0, y1, y2, y3;
                asm volatile("ld.volatile.global.v4.u32 {%0,%1,%2,%3}, [%4];"
                             : "=r"(x0), "=r"(x1), "=r"(x2), "=r"(x3)
                             : "l"(a0) : "memory");
                asm volatile("ld.volatile.global.v4.u32 {%0,%1,%2,%3}, [%4];"
                             : "=r"(y0), "=r"(y1), "=r"(y2), "=r"(y3)
                             : "l"(a1) : "memory");
                if (x0 >= target && x1 >= target && x2 >= target && x3 >= target &&
                    y0 >= target && y1 >= target && y2 >= target && y3 >= target)
                    break;
            }
            __threadfence();
        }
        __syncthreads();

        // ---- parallel gather of full h(t): 1 float4 per thread ----
        {
            const float4* src = (const float4*)g_hbuf[t & 1];
            float4* dst = (float4*)h_s;
            dst[tid] = __ldcg(&src[tid]);
        }
        __syncthreads();
    }
}

// ------------------------------------------------------------------
// Y[t][n] = b_y[n] + sum_k H[t][k] * W_y[n][k]
// ------------------------------------------------------------------
__global__ void y_kernel(const float* __restrict__ Wy, const float* __restrict__ by,
                         float* __restrict__ out)
{
    __shared__ float as[64][33];
    __shared__ float ws[64][33];
    __shared__ float bias_s[64];

    const int tid = threadIdx.x;
    const int t0 = blockIdx.x * 64;
    const int n0 = blockIdx.y * 64;
    if (tid < 64) bias_s[tid] = by[n0 + tid];

    const int tx = tid & 15, ty = tid >> 4;
    float acc[4][4];
    #pragma unroll
    for (int e = 0; e < 4; ++e)
        #pragma unroll
        for (int f = 0; f < 4; ++f) acc[e][f] = 0.f;

    for (int kc = 0; kc < HID; kc += 32) {
        __syncthreads();
        #pragma unroll
        for (int i = 0; i < 8; ++i) {
            int l = tid + 256 * i;
            int row = l >> 5, col = l & 31;
            as[row][col] = g_H[(size_t)(t0 + row) * HID + kc + col];
            ws[row][col] = Wy[(size_t)(n0 + row) * HID + kc + col];
        }
        __syncthreads();
        #pragma unroll
        for (int k = 0; k < 32; ++k) {
            float a[4], b[4];
            #pragma unroll
            for (int e = 0; e < 4; ++e) a[e] = as[ty * 4 + e][k];
            #pragma unroll
            for (int f = 0; f < 4; ++f) b[f] = ws[tx * 4 + f][k];
            #pragma unroll
            for (int e = 0; e < 4; ++e)
                #pragma unroll
                for (int f = 0; f < 4; ++f) acc[e][f] = fmaf(a[e], b[f], acc[e][f]);
        }
    }
    __syncthreads();
    #pragma unroll
    for (int e = 0; e < 4; ++e)
        #pragma unroll
        for (int f = 0; f < 4; ++f)
            out[(size_t)(t0 + ty * 4 + e) * NCH + n0 + tx * 4 + f]
                = acc[e][f] + bias_s[tx * 4 + f];
}

// ------------------------------------------------------------------
extern "C" void kernel_launch(void* const* d_in, const int* in_sizes, int n_in,
                              void* d_out, int out_size)
{
    const int*   seq = (const int*)  d_in[0];
    const float* emb = (const float*)d_in[1];
    const float* Wf  = (const float*)d_in[2];
    const float* bf  = (const float*)d_in[3];
    const float* Wi  = (const float*)d_in[4];
    const float* bi  = (const float*)d_in[5];
    const float* Wo  = (const float*)d_in[6];
    const float* bo  = (const float*)d_in[7];
    const float* Wc  = (const float*)d_in[8];
    const float* bc  = (const float*)d_in[9];
    const float* Wy  = (const float*)d_in[10];
    const float* by  = (const float*)d_in[11];
    float* out = (float*)d_out;

    const int dyn_smem = SROWS * HID * 2 + HID * 4;   // 204800 B
    cudaFuncSetAttribute(lstm_loop, cudaFuncAttributeMaxDynamicSharedMemorySize, dyn_smem);

    init_kernel<<<1, 256>>>();

    prep_kernel<<<4 * HID, 256>>>(Wf, Wi, Wc, Wo);

    dim3 ggx(T_LEN / 64, (4 * HID) / 64);          // 128 x 128
    gx_kernel<<<ggx, 256>>>(seq, emb, Wf, Wi, Wc, Wo, bf, bi, bc, bo);

    lstm_loop<<<NBLK, NTHR, dyn_smem>>>(out);

    dim3 gy(T_LEN / 64, NCH / 64);                 // 128 x 4
    y_kernel<<<gy, 256>>>(Wy, by, out);
}